// round 2
// baseline (speedup 1.0000x reference)
#include <cuda_runtime.h>

#define N_B 16
#define IC  256
#define OC  256
#define HH  64
#define WW  64
#define SD  512
#define EPSV 1e-8f

// ---- scratch (device globals; no allocations allowed) ----
__device__ float g_m[N_B * IC];          // (style @ mod_w^T + bias) + 1
__device__ float g_demod[N_B * OC];      // rsqrt(sum_i m^2 * wsq + eps)
__device__ float g_wsq[IC * OC];         // [i][o] : sum over 9 taps of weight^2
__device__ float g_wt[OC * IC * 9];      // [ocb(8)][ic(256)][tap(9)][oc32(32)]

// ---------------------------------------------------------------------------
// Kernel 1: m[n,i] = style[n] . mod_w[i] + mod_b[i] + 1
// ---------------------------------------------------------------------------
__global__ void mod_kernel(const float* __restrict__ style,
                           const float* __restrict__ mod_w,
                           const float* __restrict__ mod_b) {
    int n = blockIdx.x;
    int i = threadIdx.x;
    __shared__ float ss[SD];
    for (int k = threadIdx.x; k < SD; k += blockDim.x) ss[k] = style[n * SD + k];
    __syncthreads();
    float acc = 0.f;
    const float* wr = mod_w + i * SD;
#pragma unroll 8
    for (int k = 0; k < SD; k++) acc += ss[k] * wr[k];
    g_m[n * IC + i] = acc + mod_b[i] + 1.0f;
}

// ---------------------------------------------------------------------------
// Kernel 2: wsq[i][o] = sum_t weight[o,i,t]^2
// ---------------------------------------------------------------------------
__global__ void wsq_kernel(const float* __restrict__ weight) {
    int i = blockIdx.x;
    int o = threadIdx.x;
    const float* w = weight + (o * IC + i) * 9;
    float s = 0.f;
#pragma unroll
    for (int t = 0; t < 9; t++) s += w[t] * w[t];
    g_wsq[i * OC + o] = s;
}

// ---------------------------------------------------------------------------
// Kernel 3: demod[n,o] = rsqrt( sum_i m[n,i]^2 * wsq[i][o] + eps )
// ---------------------------------------------------------------------------
__global__ void demod_kernel() {
    int n = blockIdx.x;
    int o = threadIdx.x;
    __shared__ float ms[IC];
    ms[threadIdx.x] = g_m[n * IC + threadIdx.x];
    __syncthreads();
    float acc = EPSV;
#pragma unroll 8
    for (int i = 0; i < IC; i++) acc += ms[i] * ms[i] * g_wsq[i * OC + o];
    g_demod[n * OC + o] = rsqrtf(acc);
}

// ---------------------------------------------------------------------------
// Kernel 4: transpose weights into [ocb][ic][tap][oc32] (coalesced SMEM fills)
// ---------------------------------------------------------------------------
__global__ void wt_kernel(const float* __restrict__ weight) {
    int idx = blockIdx.x * 256 + threadIdx.x;          // 0 .. 589823
    int oc32 = idx & 31;
    int tmp  = idx >> 5;
    int tap  = tmp % 9;  tmp /= 9;
    int ic   = tmp & 255;
    int ocb  = tmp >> 8;
    int o = ocb * 32 + oc32;
    g_wt[idx] = weight[(o * IC + ic) * 9 + tap];
}

// ---------------------------------------------------------------------------
// Kernel 5: main conv. CTA tile: 32 oc x (8 rows x 32 cols) pixels.
// Thread: 4 oc x 8 px. K-loop: 32 chunks of 8 input channels,
// register-staged double buffering. Input modulation (x * m) folded into
// the SMEM fill; demod folded into the epilogue.
// ---------------------------------------------------------------------------
#define OC_T 32
#define TH 8
#define TW 32
#define ICC 8
#define XS 34                    // smem row stride (floats) -> conflict-free LDS.64
#define XROWS 10
#define XPLANE (XROWS * XS)      // 340
#define XTOT (ICC * XPLANE)      // 2720
#define WTOT (ICC * 9 * OC_T)    // 2304
#define NCHUNK (IC / ICC)        // 32

__global__ __launch_bounds__(256, 2)
void conv_kernel(const float* __restrict__ x, float* __restrict__ out) {
    __shared__ __align__(16) float xs[2][XTOT];
    __shared__ __align__(16) float ws[2][WTOT];

    const int n   = blockIdx.z;
    const int ocb = blockIdx.y;
    const int sp  = blockIdx.x;            // 0..15
    const int ht  = sp >> 1, wt = sp & 1;
    const int h0  = ht * TH, w0 = wt * TW;

    const int tid  = threadIdx.x;
    const int ocg  = tid >> 5;             // 0..7  (4 oc each)
    const int pg   = tid & 31;             // 0..31
    const int prow = pg >> 2;              // 0..7
    const int pcol = (pg & 3) << 3;        // 0,8,16,24

    const float* xbase = x + (size_t)(n * IC) * (HH * WW);
    const float* mrow  = g_m + n * IC;

    float acc[4][8];
#pragma unroll
    for (int o = 0; o < 4; o++)
#pragma unroll
        for (int p = 0; p < 8; p++) acc[o][p] = 0.f;

    float xstg[11];
    float wstg[9];

    // ---- stage chunk 0 ----
    {
        const int icb = 0;
        const float* wsrc = g_wt + (ocb * IC + icb) * 288;
#pragma unroll
        for (int k = 0; k < 9; k++) wstg[k] = wsrc[tid + k * 256];
#pragma unroll
        for (int k = 0; k < 11; k++) {
            int e = tid + k * 256;
            float v = 0.f;
            if (e < XTOT) {
                int c  = e % XS;
                int rr = (e / XS) % XROWS;
                int ic = e / XPLANE;
                int gh = h0 + rr - 1;
                int gw = w0 + c - 1;
                if ((unsigned)gh < HH && (unsigned)gw < WW)
                    v = xbase[(icb + ic) * (HH * WW) + gh * WW + gw] * mrow[icb + ic];
            }
            xstg[k] = v;
        }
    }
    // ---- commit chunk 0 -> buf 0 ----
#pragma unroll
    for (int k = 0; k < 9; k++) ws[0][tid + k * 256] = wstg[k];
#pragma unroll
    for (int k = 0; k < 11; k++) {
        int e = tid + k * 256;
        if (e < XTOT) xs[0][e] = xstg[k];
    }
    __syncthreads();

    for (int chunk = 0; chunk < NCHUNK; chunk++) {
        const int buf = chunk & 1;

        // stage next chunk into registers (overlaps with compute below)
        if (chunk + 1 < NCHUNK) {
            const int icb = (chunk + 1) * ICC;
            const float* wsrc = g_wt + (ocb * IC + icb) * 288;
#pragma unroll
            for (int k = 0; k < 9; k++) wstg[k] = wsrc[tid + k * 256];
#pragma unroll
            for (int k = 0; k < 11; k++) {
                int e = tid + k * 256;
                float v = 0.f;
                if (e < XTOT) {
                    int c  = e % XS;
                    int rr = (e / XS) % XROWS;
                    int ic = e / XPLANE;
                    int gh = h0 + rr - 1;
                    int gw = w0 + c - 1;
                    if ((unsigned)gh < HH && (unsigned)gw < WW)
                        v = xbase[(icb + ic) * (HH * WW) + gh * WW + gw] * mrow[icb + ic];
                }
                xstg[k] = v;
            }
        }

        // ---- compute on current buffer ----
#pragma unroll 2
        for (int ic = 0; ic < ICC; ic++) {
            const float* xp = &xs[buf][ic * XPLANE + prow * XS + pcol];
#pragma unroll
            for (int kh = 0; kh < 3; kh++) {
                float xv[10];
                const float2* xp2 = (const float2*)(xp + kh * XS);
#pragma unroll
                for (int j = 0; j < 5; j++) {
                    float2 t = xp2[j];
                    xv[2 * j] = t.x;
                    xv[2 * j + 1] = t.y;
                }
#pragma unroll
                for (int kw = 0; kw < 3; kw++) {
                    // warp-uniform broadcast load (ocg constant within warp)
                    const float4 wv4 = *(const float4*)&ws[buf][((ic * 3 + kh) * 3 + kw) * 32 + ocg * 4];
                    const float wv[4] = {wv4.x, wv4.y, wv4.z, wv4.w};
#pragma unroll
                    for (int o = 0; o < 4; o++)
#pragma unroll
                        for (int p = 0; p < 8; p++)
                            acc[o][p] += wv[o] * xv[kw + p];
                }
            }
        }

        // commit next chunk into the other buffer, then one barrier
        if (chunk + 1 < NCHUNK) {
            const int nb = buf ^ 1;
#pragma unroll
            for (int k = 0; k < 9; k++) ws[nb][tid + k * 256] = wstg[k];
#pragma unroll
            for (int k = 0; k < 11; k++) {
                int e = tid + k * 256;
                if (e < XTOT) xs[nb][e] = xstg[k];
            }
        }
        __syncthreads();
    }

    // ---- epilogue: scale by demod, vectorized stores ----
#pragma unroll
    for (int o = 0; o < 4; o++) {
        const int oc = ocb * 32 + ocg * 4 + o;
        const float d = g_demod[n * OC + oc];
        float* orow = out + (((size_t)(n * OC + oc)) * HH + (h0 + prow)) * WW + w0 + pcol;
        float4 v0, v1;
        v0.x = acc[o][0] * d; v0.y = acc[o][1] * d; v0.z = acc[o][2] * d; v0.w = acc[o][3] * d;
        v1.x = acc[o][4] * d; v1.y = acc[o][5] * d; v1.z = acc[o][6] * d; v1.w = acc[o][7] * d;
        ((float4*)orow)[0] = v0;
        ((float4*)orow)[1] = v1;
    }
}

// ---------------------------------------------------------------------------
extern "C" void kernel_launch(void* const* d_in, const int* in_sizes, int n_in,
                              void* d_out, int out_size) {
    const float* x      = (const float*)d_in[0];
    const float* style  = (const float*)d_in[1];
    const float* weight = (const float*)d_in[2];
    const float* mod_w  = (const float*)d_in[3];
    const float* mod_b  = (const float*)d_in[4];
    float* out = (float*)d_out;

    mod_kernel<<<N_B, 256>>>(style, mod_w, mod_b);
    wsq_kernel<<<IC, 256>>>(weight);
    demod_kernel<<<N_B, 256>>>();
    wt_kernel<<<(OC * IC * 9) / 256, 256>>>(weight);

    dim3 grid(16, 8, N_B);   // 16 spatial tiles, 8 oc tiles, 16 samples
    conv_kernel<<<grid, 256>>>(x, out);
}

// round 4
// speedup vs baseline: 1.8665x; 1.8665x over previous
#include <cuda_runtime.h>
#include <cuda_fp16.h>
#include <cstdint>

#define N_B 16
#define IC  256
#define OC  256
#define HH  64
#define WW  64
#define SD  512
#define EPSV 1e-8f
#define NCHUNKS 36

// ---------------- device scratch ----------------
__device__ float g_m[N_B * IC];
__device__ float g_demod[N_B * OC];
__device__ float g_wsq[IC * OC];
// [chunk(36)][nhalf(2)][plane hi/lo(2)][oc128*64k swizzled] fp16
__device__ __half g_wB[NCHUNKS * 2 * 2 * 8192];

// ---------------- smem layout (dynamic) ----------------
#define SM_B   0            // 2 stages x 32768 (hi 16KB + lo 16KB per stage)
#define SM_PH  65536        // patch hi: 4*66*64 fp16 = 33792 B
#define SM_PL  99328        // patch lo
#define SM_MS  133120       // 256 f32 modulation
#define SM_DS  134144       // 256 f32 demod
#define SMEM_BYTES 135168
#define PL_DELTA 33792

// ---------------- PTX helpers ----------------
__device__ __forceinline__ uint32_t smem_u32(const void* p) {
    uint32_t a;
    asm("{ .reg .u64 t; cvta.to.shared.u64 t, %1; cvt.u32.u64 %0, t; }" : "=r"(a) : "l"(p));
    return a;
}
#define LDSM_X4(r0, r1, r2, r3, addr) \
    asm volatile("ldmatrix.sync.aligned.m8n8.x4.shared.b16 {%0,%1,%2,%3}, [%4];" \
        : "=r"(r0), "=r"(r1), "=r"(r2), "=r"(r3) : "r"(addr))
#define MMA16816(c, a, b0, b1) \
    asm volatile("mma.sync.aligned.m16n8k16.row.col.f32.f16.f16.f32 " \
        "{%0,%1,%2,%3}, {%4,%5,%6,%7}, {%8,%9}, {%0,%1,%2,%3};" \
        : "+f"((c)[0]), "+f"((c)[1]), "+f"((c)[2]), "+f"((c)[3]) \
        : "r"((a)[0]), "r"((a)[1]), "r"((a)[2]), "r"((a)[3]), "r"(b0), "r"(b1))
#define CP_ASYNC16(dst, src) \
    asm volatile("cp.async.cg.shared.global [%0], [%1], 16;" :: "r"(dst), "l"(src))
#define CP_COMMIT() asm volatile("cp.async.commit_group;")

// ---------------- prep kernels ----------------
__global__ void mod_kernel(const float* __restrict__ style,
                           const float* __restrict__ mod_w,
                           const float* __restrict__ mod_b) {
    int n = blockIdx.x, i = threadIdx.x;
    __shared__ float ss[SD];
    for (int k = threadIdx.x; k < SD; k += blockDim.x) ss[k] = style[n * SD + k];
    __syncthreads();
    float acc = 0.f;
    const float* wr = mod_w + i * SD;
#pragma unroll 8
    for (int k = 0; k < SD; k++) acc += ss[k] * wr[k];
    g_m[n * IC + i] = acc + mod_b[i] + 1.0f;
}

__global__ void wsq_kernel(const float* __restrict__ weight) {
    int i = blockIdx.x, o = threadIdx.x;
    const float* w = weight + (o * IC + i) * 9;
    float s = 0.f;
#pragma unroll
    for (int t = 0; t < 9; t++) s += w[t] * w[t];
    g_wsq[i * OC + o] = s;
}

__global__ void demod_kernel() {
    int n = blockIdx.x, o = threadIdx.x;
    __shared__ float ms[IC];
    ms[threadIdx.x] = g_m[n * IC + threadIdx.x];
    __syncthreads();
    float acc = EPSV;
#pragma unroll 8
    for (int i = 0; i < IC; i++) acc += ms[i] * ms[i] * g_wsq[i * OC + o];
    g_demod[n * OC + o] = rsqrtf(acc);
}

// split weights into fp16 hi/lo in swizzled B-tile layout
__global__ void wsplit_kernel(const float* __restrict__ weight) {
    int idx = blockIdx.x * 256 + threadIdx.x;   // 0 .. 589823
    int kl    = idx & 7;
    int gs    = (idx >> 3) & 7;
    int oc128 = (idx >> 6) & 127;
    int nh    = (idx >> 13) & 1;
    int chunk = idx >> 14;
    int tap = chunk % 9, icb = chunk / 9;
    int kg = gs ^ (oc128 & 7);
    int ic = icb * 64 + kg * 8 + kl;
    int oc = nh * 128 + oc128;
    float w = weight[(oc * IC + ic) * 9 + tap];
    __half h = __float2half_rn(w);
    __half l = __float2half_rn(w - __half2float(h));
    size_t base = (size_t)((chunk * 2 + nh) * 2) * 8192;
    size_t off = (size_t)oc128 * 64 + gs * 8 + kl;
    g_wB[base + off] = h;
    g_wB[base + 8192 + off] = l;
}

// ---------------- main conv: mma.sync implicit GEMM ----------------
__global__ __launch_bounds__(256, 1)
void conv_mma(const float* __restrict__ x, float* __restrict__ out) {
    extern __shared__ __align__(128) unsigned char smem[];
    const uint32_t sb = smem_u32(smem);
    const int tid = threadIdx.x;
    const int wid = tid >> 5, lane = tid & 31;
    const int bx = blockIdx.x;
    const int n = bx >> 5, tile = bx & 31;
    const int h0 = tile * 2;
    const int nh = blockIdx.y;

    float* msf = (float*)(smem + SM_MS);
    float* dsf = (float*)(smem + SM_DS);
    msf[tid] = g_m[n * IC + tid];
    dsf[tid] = g_demod[n * OC + tid];

    const float* xb = x + (size_t)n * IC * HH * WW;

    const int warp_m = wid & 3, warp_n = wid >> 2;
    // A lane mapping (ldmatrix x4: lanes 0-15 rows, lane>>4 selects k-granule)
    const int pxr0 = warp_m * 32 + (lane & 15);
    const int aksel = lane >> 4;
    // B lane mapping
    const uint32_t bboff = (uint32_t)(warp_n * 64 + ((lane >> 4) << 3) + (lane & 7)) * 128;
    const int bksel = (lane >> 3) & 1;
    const int bswz = lane & 7;

    float acc[2][8][4];
#pragma unroll
    for (int a = 0; a < 2; a++)
#pragma unroll
        for (int b = 0; b < 8; b++)
#pragma unroll
            for (int q = 0; q < 4; q++) acc[a][b][q] = 0.f;

    // prologue: copy B chunk 0 -> stage 0
    {
        const char* src = (const char*)(g_wB + (size_t)((0 * 2 + nh) * 2) * 8192);
        uint32_t dst = sb + SM_B;
#pragma unroll
        for (int i = 0; i < 8; i++)
            CP_ASYNC16(dst + tid * 16 + i * 4096, src + tid * 16 + i * 4096);
        CP_COMMIT();
    }

#pragma unroll 1
    for (int icb = 0; icb < 4; icb++) {
#pragma unroll 1
        for (int tap = 0; tap < 9; tap++) {
            const int c = icb * 9 + tap;
            const int s = c & 1;
            const int kh = tap / 3, kw = tap - kh * 3;

            __syncthreads();   // previous chunk's compute (and patch reads) done

            if (c + 1 < NCHUNKS) {
                const char* src = (const char*)(g_wB + (size_t)(((c + 1) * 2 + nh) * 2) * 8192);
                uint32_t dst = sb + SM_B + (s ^ 1) * 32768;
#pragma unroll
                for (int i = 0; i < 8; i++)
                    CP_ASYNC16(dst + tid * 16 + i * 4096, src + tid * 16 + i * 4096);
                CP_COMMIT();
            }

            if (tap == 0) {
                // refill x patch: [4 rows][66 cols][64 ic] hi/lo, swizzled
                uint32_t* Hp = (uint32_t*)(smem + SM_PH);
                uint32_t* Lp = (uint32_t*)(smem + SM_PL);
                for (int idx = tid; idx < 8448; idx += 256) {
                    int cc = idx % 66;
                    int t2 = idx / 66;
                    int icp = t2 & 31, r = t2 >> 5;
                    int gh = h0 + r - 1, gw = cc - 1;
                    int ic = icb * 64 + icp * 2;
                    float v0 = 0.f, v1 = 0.f;
                    if ((unsigned)gh < HH && (unsigned)gw < WW) {
                        const float* p = xb + (size_t)ic * 4096 + gh * 64 + gw;
                        v0 = p[0] * msf[ic];
                        v1 = p[4096] * msf[ic + 1];
                    }
                    __half2 h2 = __floats2half2_rn(v0, v1);
                    float r0 = __half2float(__low2half(h2));
                    float r1 = __half2float(__high2half(h2));
                    __half2 l2 = __floats2half2_rn(v0 - r0, v1 - r1);
                    int slot = (icp >> 2) ^ (cc & 7);
                    int off = (r * 66 + cc) * 32 + slot * 4 + (icp & 3);
                    Hp[off] = *(uint32_t*)&h2;
                    Lp[off] = *(uint32_t*)&l2;
                }
            }

            if (c + 1 < NCHUNKS) asm volatile("cp.async.wait_group 1;");
            else                 asm volatile("cp.async.wait_group 0;");
            __syncthreads();

            // ---- compute chunk c ----
            uint32_t aoffH[2];
            int acsw[2];
#pragma unroll
            for (int mt = 0; mt < 2; mt++) {
                int px = pxr0 + mt * 16;
                int r = (px >> 6) + kh, cq = (px & 63) + kw;
                aoffH[mt] = sb + SM_PH + (uint32_t)(r * 66 + cq) * 128;
                acsw[mt] = cq & 7;
            }
            const uint32_t bHbase = sb + SM_B + s * 32768 + bboff;

#pragma unroll
            for (int st = 0; st < 4; st++) {
                uint32_t AH[2][4], AL[2][4], BH[4][4], BL[4][4];
#pragma unroll
                for (int mt = 0; mt < 2; mt++) {
                    int kg = 2 * st + aksel;
                    uint32_t a = aoffH[mt] + (uint32_t)((kg ^ acsw[mt]) << 4);
                    LDSM_X4(AH[mt][0], AH[mt][1], AH[mt][2], AH[mt][3], a);
                    LDSM_X4(AL[mt][0], AL[mt][1], AL[mt][2], AL[mt][3], a + PL_DELTA);
                }
                {
                    int kg = 2 * st + bksel;
                    uint32_t boff = (uint32_t)((kg ^ bswz) << 4);
#pragma unroll
                    for (int og = 0; og < 4; og++) {
                        uint32_t a = bHbase + og * 2048 + boff;
                        LDSM_X4(BH[og][0], BH[og][1], BH[og][2], BH[og][3], a);
                        LDSM_X4(BL[og][0], BL[og][1], BL[og][2], BL[og][3], a + 16384);
                    }
                }
#pragma unroll
                for (int og = 0; og < 4; og++)
#pragma unroll
                    for (int mt = 0; mt < 2; mt++) {
                        MMA16816(acc[mt][og * 2],     AH[mt], BH[og][0], BH[og][1]);
                        MMA16816(acc[mt][og * 2],     AL[mt], BH[og][0], BH[og][1]);
                        MMA16816(acc[mt][og * 2],     AH[mt], BL[og][0], BL[og][1]);
                        MMA16816(acc[mt][og * 2 + 1], AH[mt], BH[og][2], BH[og][3]);
                        MMA16816(acc[mt][og * 2 + 1], AL[mt], BH[og][2], BH[og][3]);
                        MMA16816(acc[mt][og * 2 + 1], AH[mt], BL[og][2], BL[og][3]);
                    }
            }
        }
    }

    // ---- epilogue: demod scale + store ----
    float* outb = out + (size_t)n * OC * HH * WW + h0 * 64;
#pragma unroll
    for (int mt = 0; mt < 2; mt++) {
        int px0 = warp_m * 32 + mt * 16 + (lane >> 2);
#pragma unroll
        for (int nt = 0; nt < 8; nt++) {
            int oc = nh * 128 + warp_n * 64 + nt * 8 + (lane & 3) * 2;
            float d0 = dsf[oc], d1 = dsf[oc + 1];
            float* p0 = outb + (size_t)oc * 4096;
            p0[px0]            = acc[mt][nt][0] * d0;
            p0[4096 + px0]     = acc[mt][nt][1] * d1;
            p0[px0 + 8]        = acc[mt][nt][2] * d0;
            p0[4096 + px0 + 8] = acc[mt][nt][3] * d1;
        }
    }
}

// ---------------------------------------------------------------------------
extern "C" void kernel_launch(void* const* d_in, const int* in_sizes, int n_in,
                              void* d_out, int out_size) {
    const float* x      = (const float*)d_in[0];
    const float* style  = (const float*)d_in[1];
    const float* weight = (const float*)d_in[2];
    const float* mod_w  = (const float*)d_in[3];
    const float* mod_b  = (const float*)d_in[4];
    float* out = (float*)d_out;

    cudaFuncSetAttribute(conv_mma, cudaFuncAttributeMaxDynamicSharedMemorySize, SMEM_BYTES);

    mod_kernel<<<N_B, 256>>>(style, mod_w, mod_b);
    wsq_kernel<<<IC, 256>>>(weight);
    demod_kernel<<<N_B, 256>>>();
    wsplit_kernel<<<(NCHUNKS * 2 * 8192) / 256, 256>>>(weight);

    dim3 grid(512, 2);
    conv_mma<<<grid, 256, SMEM_BYTES>>>(x, out);
}

// round 5
// speedup vs baseline: 4.2333x; 2.2681x over previous
#include <cuda_runtime.h>
#include <cuda_fp16.h>
#include <cstdint>

#define N_B 16
#define IC  256
#define OC  256
#define HH  64
#define WW  64
#define SD  512
#define EPSV 1e-8f

// ---------------- device scratch ----------------
__device__ float g_m[N_B * IC];
__device__ float g_demod[N_B * OC];
__device__ float g_wsq[IC * OC];
// V: [pt(36)][mblock(32)][kc(4)][plane(2)][128 rows x 64 ic swizzled] fp16
__device__ __align__(16) __half g_V[36 * 32 * 4 * 2 * 8192];
// U: [pt(36)][nh(2)][kc(4)][plane(2)][128 oc x 64 ic swizzled] fp16
__device__ __align__(16) __half g_U[36 * 2 * 4 * 2 * 8192];
// M: [pt(36)][oc(256)][flat_tile(4096)] fp32
__device__ float g_M[36 * 256 * 4096];

// ---------------- PTX helpers ----------------
__device__ __forceinline__ uint32_t smem_u32(const void* p) {
    uint32_t a;
    asm("{ .reg .u64 t; cvta.to.shared.u64 t, %1; cvt.u32.u64 %0, t; }" : "=r"(a) : "l"(p));
    return a;
}
#define LDSM_X4(r0, r1, r2, r3, addr) \
    asm volatile("ldmatrix.sync.aligned.m8n8.x4.shared.b16 {%0,%1,%2,%3}, [%4];" \
        : "=r"(r0), "=r"(r1), "=r"(r2), "=r"(r3) : "r"(addr))
#define MMA16816(c, a, b0, b1) \
    asm volatile("mma.sync.aligned.m16n8k16.row.col.f32.f16.f16.f32 " \
        "{%0,%1,%2,%3}, {%4,%5,%6,%7}, {%8,%9}, {%0,%1,%2,%3};" \
        : "+f"((c)[0]), "+f"((c)[1]), "+f"((c)[2]), "+f"((c)[3]) \
        : "r"((a)[0]), "r"((a)[1]), "r"((a)[2]), "r"((a)[3]), "r"(b0), "r"(b1))
#define CP_ASYNC16(dst, src) \
    asm volatile("cp.async.cg.shared.global [%0], [%1], 16;" :: "r"(dst), "l"(src))
#define CP_COMMIT() asm volatile("cp.async.commit_group;")

// ---------------- prep kernels ----------------
__global__ void mod_kernel(const float* __restrict__ style,
                           const float* __restrict__ mod_w,
                           const float* __restrict__ mod_b) {
    int n = blockIdx.x, i = threadIdx.x;
    __shared__ float ss[SD];
    for (int k = threadIdx.x; k < SD; k += blockDim.x) ss[k] = style[n * SD + k];
    __syncthreads();
    float acc = 0.f;
    const float* wr = mod_w + i * SD;
#pragma unroll 8
    for (int k = 0; k < SD; k++) acc += ss[k] * wr[k];
    g_m[n * IC + i] = acc + mod_b[i] + 1.0f;
}

__global__ void wsq_kernel(const float* __restrict__ weight) {
    int i = blockIdx.x, o = threadIdx.x;
    const float* w = weight + (o * IC + i) * 9;
    float s = 0.f;
#pragma unroll
    for (int t = 0; t < 9; t++) s += w[t] * w[t];
    g_wsq[i * OC + o] = s;
}

__global__ void demod_kernel() {
    int n = blockIdx.x, o = threadIdx.x;
    __shared__ float ms[IC];
    ms[threadIdx.x] = g_m[n * IC + threadIdx.x];
    __syncthreads();
    float acc = EPSV;
#pragma unroll 8
    for (int i = 0; i < IC; i++) acc += ms[i] * ms[i] * g_wsq[i * OC + o];
    g_demod[n * OC + o] = rsqrtf(acc);
}

// ---------------- weight transform: U = G g G^T, split + swizzle ----------------
__global__ void wT_kernel(const float* __restrict__ weight) {
    int idx = blockIdx.x * 256 + threadIdx.x;   // 0..65535
    int oc = idx >> 8, ic = idx & 255;
    float g[3][3];
#pragma unroll
    for (int r = 0; r < 3; r++)
#pragma unroll
        for (int c = 0; c < 3; c++) g[r][c] = weight[(oc * IC + ic) * 9 + r * 3 + c];

    float t[6][3];
#pragma unroll
    for (int c = 0; c < 3; c++) {
        float g0 = g[0][c], g1 = g[1][c], g2 = g[2][c];
        t[0][c] = 0.25f * g0;
        t[1][c] = (-g0 - g1 - g2) * (1.f / 6.f);
        t[2][c] = (-g0 + g1 - g2) * (1.f / 6.f);
        t[3][c] = g0 * (1.f / 24.f) + g1 * (1.f / 12.f) + g2 * (1.f / 6.f);
        t[4][c] = g0 * (1.f / 24.f) - g1 * (1.f / 12.f) + g2 * (1.f / 6.f);
        t[5][c] = g2;
    }
    const int nh = oc >> 7, oc128 = oc & 127;
    const int kc = ic >> 6, icc = ic & 63, kg = icc >> 3, kl = icc & 7;
    const int off16 = oc128 * 64 + ((kg ^ (oc128 & 7)) << 3) + kl;
#pragma unroll
    for (int r = 0; r < 6; r++) {
        float t0 = t[r][0], t1 = t[r][1], t2 = t[r][2];
        float u[6];
        u[0] = 0.25f * t0;
        u[1] = (-t0 - t1 - t2) * (1.f / 6.f);
        u[2] = (-t0 + t1 - t2) * (1.f / 6.f);
        u[3] = t0 * (1.f / 24.f) + t1 * (1.f / 12.f) + t2 * (1.f / 6.f);
        u[4] = t0 * (1.f / 24.f) - t1 * (1.f / 12.f) + t2 * (1.f / 6.f);
        u[5] = t2;
#pragma unroll
        for (int c = 0; c < 6; c++) {
            int pt = r * 6 + c;
            __half h = __float2half_rn(u[c]);
            __half l = __float2half_rn(u[c] - __half2float(h));
            size_t base = ((size_t)(((pt * 2 + nh) * 4 + kc) * 2)) * 8192;
            g_U[base + off16] = h;
            g_U[base + 8192 + off16] = l;
        }
    }
}

// ---------------- input transform: V = B^T (x*m) B, split + swizzle ----------------
__global__ __launch_bounds__(256) void inT_kernel(const float* __restrict__ x) {
    const int icg = blockIdx.x;    // 16-ic group (0..15)
    const int th  = blockIdx.y;    // tile row (0..15)
    const int n   = blockIdx.z;
    const int tid = threadIdx.x;
    const int tw  = tid & 15, icl = tid >> 4;
    const int ic  = icg * 16 + icl;

    const float mm = g_m[n * IC + ic];
    const float* xp = x + ((size_t)(n * IC + ic)) * 4096;

    float d[6][6];
#pragma unroll
    for (int r = 0; r < 6; r++) {
        int gh = th * 4 + r - 1;
#pragma unroll
        for (int c = 0; c < 6; c++) {
            int gw = tw * 4 + c - 1;
            d[r][c] = ((unsigned)gh < HH && (unsigned)gw < WW) ? xp[gh * 64 + gw] * mm : 0.f;
        }
    }
    // t = BT * d  (column transform)
    float t[6][6];
#pragma unroll
    for (int c = 0; c < 6; c++) {
        float d0 = d[0][c], d1 = d[1][c], d2 = d[2][c], d3 = d[3][c], d4 = d[4][c], d5 = d[5][c];
        t[0][c] = 4.f * d0 - 5.f * d2 + d4;
        t[1][c] = -4.f * d1 - 4.f * d2 + d3 + d4;
        t[2][c] = 4.f * d1 - 4.f * d2 - d3 + d4;
        t[3][c] = -2.f * d1 - d2 + 2.f * d3 + d4;
        t[4][c] = 2.f * d1 - d2 - 2.f * d3 + d4;
        t[5][c] = 4.f * d1 - 5.f * d3 + d5;
    }

    __shared__ __align__(16) __half stH[6][16][16];
    __shared__ __align__(16) __half stL[6][16][16];

    const int mb = n * 2 + (th >> 3);
    const int kc = icg >> 2;
    const int rowbase = (th & 7) * 16;

#pragma unroll 1
    for (int r = 0; r < 6; r++) {
        float t0 = t[r][0], t1 = t[r][1], t2 = t[r][2], t3 = t[r][3], t4 = t[r][4], t5 = t[r][5];
        float v[6];
        v[0] = 4.f * t0 - 5.f * t2 + t4;
        v[1] = -4.f * t1 - 4.f * t2 + t3 + t4;
        v[2] = 4.f * t1 - 4.f * t2 - t3 + t4;
        v[3] = -2.f * t1 - t2 + 2.f * t3 + t4;
        v[4] = 2.f * t1 - t2 - 2.f * t3 + t4;
        v[5] = 4.f * t1 - 5.f * t3 + t5;
#pragma unroll
        for (int c = 0; c < 6; c++) {
            __half h = __float2half_rn(v[c]);
            __half l = __float2half_rn(v[c] - __half2float(h));
            stH[c][tw][icl] = h;
            stL[c][tw][icl] = l;
        }
        __syncthreads();
        // flush 6 pts x 2 planes x 16 rows x 2 granules = 384 uint4 stores
        for (int it = tid; it < 384; it += 256) {
            int c = it / 64;
            int rest = it & 63;
            int plane = rest >> 5;
            int e = rest & 31;
            int rw = e >> 1, gsel = e & 1;
            int pt = r * 6 + c;
            int kg = (icg & 3) * 2 + gsel;
            size_t base = ((size_t)(((pt * 32 + mb) * 4 + kc) * 2 + plane)) * 8192;
            const uint4* src = plane ? (const uint4*)&stL[c][rw][gsel * 8]
                                     : (const uint4*)&stH[c][rw][gsel * 8];
            *(uint4*)(g_V + base + (rowbase + rw) * 64 + ((kg ^ (rw & 7)) << 3)) = *src;
        }
        __syncthreads();
    }
}

// ---------------- batched GEMM: M[pt] = V[pt] * U[pt]^T  (3-term fp16) ----------------
#define SMEM_G 131072
__global__ __launch_bounds__(256, 1)
void wino_gemm() {
    extern __shared__ __align__(128) unsigned char smem[];
    const uint32_t sb = smem_u32(smem);
    const int tid = threadIdx.x;
    const int wid = tid >> 5, lane = tid & 31;
    const int mb = blockIdx.x;     // 0..31
    const int nh = blockIdx.y;     // 0..1
    const int pt = blockIdx.z;     // 0..35

    const int warp_m = wid & 3, warp_n = wid >> 2;
    const int pxr0 = warp_m * 32 + (lane & 15);
    const int aksel = lane >> 4;
    const uint32_t bboff = (uint32_t)(warp_n * 64 + ((lane >> 4) << 3) + (lane & 7)) * 128;
    const int bksel = (lane >> 3) & 1;
    const int bswz = lane & 7;

    float acc[2][8][4];
#pragma unroll
    for (int a = 0; a < 2; a++)
#pragma unroll
        for (int b = 0; b < 8; b++)
#pragma unroll
            for (int q = 0; q < 4; q++) acc[a][b][q] = 0.f;

    // prologue: chunk 0 -> stage 0
    {
        const char* As = (const char*)(g_V + ((size_t)(((pt * 32 + mb) * 4 + 0) * 2)) * 8192);
        const char* Bs = (const char*)(g_U + ((size_t)(((pt * 2 + nh) * 4 + 0) * 2)) * 8192);
#pragma unroll
        for (int i = 0; i < 8; i++) CP_ASYNC16(sb + tid * 16 + i * 4096, As + tid * 16 + i * 4096);
#pragma unroll
        for (int i = 0; i < 8; i++) CP_ASYNC16(sb + 32768 + tid * 16 + i * 4096, Bs + tid * 16 + i * 4096);
        CP_COMMIT();
    }

#pragma unroll 1
    for (int kc = 0; kc < 4; kc++) {
        const int s = kc & 1;
        __syncthreads();
        if (kc + 1 < 4) {
            const char* As = (const char*)(g_V + ((size_t)(((pt * 32 + mb) * 4 + kc + 1) * 2)) * 8192);
            const char* Bs = (const char*)(g_U + ((size_t)(((pt * 2 + nh) * 4 + kc + 1) * 2)) * 8192);
            uint32_t dA = sb + (s ^ 1) * 65536;
#pragma unroll
            for (int i = 0; i < 8; i++) CP_ASYNC16(dA + tid * 16 + i * 4096, As + tid * 16 + i * 4096);
#pragma unroll
            for (int i = 0; i < 8; i++) CP_ASYNC16(dA + 32768 + tid * 16 + i * 4096, Bs + tid * 16 + i * 4096);
            CP_COMMIT();
            asm volatile("cp.async.wait_group 1;");
        } else {
            asm volatile("cp.async.wait_group 0;");
        }
        __syncthreads();

        const uint32_t Abase = sb + s * 65536;
        const uint32_t Bbase = Abase + 32768 + bboff;
#pragma unroll
        for (int st = 0; st < 4; st++) {
            uint32_t AH[2][4], AL[2][4], BH[4][4], BL[4][4];
#pragma unroll
            for (int mt = 0; mt < 2; mt++) {
                int row = pxr0 + mt * 16;
                int kg = 2 * st + aksel;
                uint32_t a = Abase + (uint32_t)row * 128 + ((uint32_t)(kg ^ (row & 7)) << 4);
                LDSM_X4(AH[mt][0], AH[mt][1], AH[mt][2], AH[mt][3], a);
                LDSM_X4(AL[mt][0], AL[mt][1], AL[mt][2], AL[mt][3], a + 16384);
            }
            {
                int kg = 2 * st + bksel;
                uint32_t boff = (uint32_t)((kg ^ bswz) << 4);
#pragma unroll
                for (int og = 0; og < 4; og++) {
                    uint32_t a = Bbase + og * 2048 + boff;
                    LDSM_X4(BH[og][0], BH[og][1], BH[og][2], BH[og][3], a);
                    LDSM_X4(BL[og][0], BL[og][1], BL[og][2], BL[og][3], a + 16384);
                }
            }
#pragma unroll
            for (int og = 0; og < 4; og++)
#pragma unroll
                for (int mt = 0; mt < 2; mt++) {
                    MMA16816(acc[mt][og * 2],     AH[mt], BH[og][0], BH[og][1]);
                    MMA16816(acc[mt][og * 2],     AL[mt], BH[og][0], BH[og][1]);
                    MMA16816(acc[mt][og * 2],     AH[mt], BL[og][0], BL[og][1]);
                    MMA16816(acc[mt][og * 2 + 1], AH[mt], BH[og][2], BH[og][3]);
                    MMA16816(acc[mt][og * 2 + 1], AL[mt], BH[og][2], BH[og][3]);
                    MMA16816(acc[mt][og * 2 + 1], AH[mt], BL[og][2], BL[og][3]);
                }
        }
    }

    // epilogue: store M (no demod here)
    float* Mp = g_M + (size_t)pt * (256 * 4096) + mb * 128;
#pragma unroll
    for (int mt = 0; mt < 2; mt++) {
        int px0 = warp_m * 32 + mt * 16 + (lane >> 2);
#pragma unroll
        for (int nt = 0; nt < 8; nt++) {
            int oc = nh * 128 + warp_n * 64 + nt * 8 + (lane & 3) * 2;
            float* p0 = Mp + (size_t)oc * 4096;
            p0[px0]            = acc[mt][nt][0];
            p0[4096 + px0]     = acc[mt][nt][1];
            p0[px0 + 8]        = acc[mt][nt][2];
            p0[4096 + px0 + 8] = acc[mt][nt][3];
        }
    }
}

// ---------------- output transform: Y = AT M A, demod, store ----------------
__global__ __launch_bounds__(256) void outT_kernel(float* __restrict__ out) {
    const int oc = blockIdx.x;
    const int n  = blockIdx.y;
    const int tid = threadIdx.x;
    const int th = tid >> 4, tw = tid & 15;
    const int flat = n * 256 + tid;

    float m6[6][6];
#pragma unroll
    for (int r = 0; r < 6; r++)
#pragma unroll
        for (int c = 0; c < 6; c++)
            m6[r][c] = g_M[(size_t)(r * 6 + c) * (256 * 4096) + (size_t)oc * 4096 + flat];

    float t2[4][6];
#pragma unroll
    for (int c = 0; c < 6; c++) {
        float m0 = m6[0][c], m1 = m6[1][c], m2 = m6[2][c], m3 = m6[3][c], m4 = m6[4][c], m5 = m6[5][c];
        t2[0][c] = m0 + m1 + m2 + m3 + m4;
        t2[1][c] = m1 - m2 + 2.f * m3 - 2.f * m4;
        t2[2][c] = m1 + m2 + 4.f * m3 + 4.f * m4;
        t2[3][c] = m1 - m2 + 8.f * m3 - 8.f * m4 + m5;
    }
    const float dm = g_demod[n * OC + oc];
    float* op = out + ((size_t)(n * OC + oc)) * 4096 + th * 4 * 64 + tw * 4;
#pragma unroll
    for (int i = 0; i < 4; i++) {
        float q0 = t2[i][0], q1 = t2[i][1], q2 = t2[i][2], q3 = t2[i][3], q4 = t2[i][4], q5 = t2[i][5];
        float4 y;
        y.x = (q0 + q1 + q2 + q3 + q4) * dm;
        y.y = (q1 - q2 + 2.f * q3 - 2.f * q4) * dm;
        y.z = (q1 + q2 + 4.f * q3 + 4.f * q4) * dm;
        y.w = (q1 - q2 + 8.f * q3 - 8.f * q4 + q5) * dm;
        *(float4*)(op + i * 64) = y;
    }
}

// ---------------------------------------------------------------------------
extern "C" void kernel_launch(void* const* d_in, const int* in_sizes, int n_in,
                              void* d_out, int out_size) {
    const float* x      = (const float*)d_in[0];
    const float* style  = (const float*)d_in[1];
    const float* weight = (const float*)d_in[2];
    const float* mod_w  = (const float*)d_in[3];
    const float* mod_b  = (const float*)d_in[4];
    float* out = (float*)d_out;

    cudaFuncSetAttribute(wino_gemm, cudaFuncAttributeMaxDynamicSharedMemorySize, SMEM_G);

    mod_kernel<<<N_B, 256>>>(style, mod_w, mod_b);
    wsq_kernel<<<IC, 256>>>(weight);
    demod_kernel<<<N_B, 256>>>();
    wT_kernel<<<256, 256>>>(weight);
    inT_kernel<<<dim3(16, 16, 16), 256>>>(x);
    wino_gemm<<<dim3(32, 2, 36), 256, SMEM_G>>>();
    outT_kernel<<<dim3(256, 16), 256>>>(out);
}